// round 8
// baseline (speedup 1.0000x reference)
#include <cuda_runtime.h>
#include <cuda_bf16.h>
#include <cstdint>

#define BATCH 16384
#define H 256
#define OUTD 10
#define IND 784
#define TSTEPS 50
#define MROWS 64
#define NTHR 256

typedef unsigned long long ull;

// -------- device scratch --------
__device__ float g_X[BATCH * H];
__device__ float g_s0[2][BATCH * OUTD];
__device__ float g_s1[2][BATCH * H];
__device__ float g_s2[2][BATCH * H];
// bf16 split weight images in [k][n] layout (n contiguous), XOR-swizzled 16B chunks.
// B1[k][n] = W2[k][n]  (P2 = rho(s1) @ W2);  B2[k][n] = W2[n][k]  (P1 = rho(s2) @ W2^T)
__device__ __nv_bfloat16 g_B1hi[H * H], g_B1lo[H * H], g_B2hi[H * H], g_B2lo[H * H];

__device__ __forceinline__ float rho_f(float x) { return fminf(fmaxf(x, 0.0f), 1.0f); }

__device__ __forceinline__ ull pack2(float a, float b) {
    ull r; asm("mov.b64 %0, {%1, %2};" : "=l"(r) : "f"(a), "f"(b)); return r;
}
__device__ __forceinline__ void fma2(ull &d, ull a, ull b) {
    asm("fma.rn.f32x2 %0, %1, %2, %0;" : "+l"(d) : "l"(a), "l"(b));
}
__device__ __forceinline__ float2 unpack2(ull v) {
    float2 f; asm("mov.b64 {%0, %1}, %2;" : "=f"(f.x), "=f"(f.y) : "l"(v)); return f;
}
__device__ __forceinline__ void cpasync16(char* dst, const char* src) {
    unsigned d = (unsigned)__cvta_generic_to_shared(dst);
    asm volatile("cp.async.cg.shared.global [%0], [%1], 16;" :: "r"(d), "l"(src));
}
__device__ __forceinline__ void cpasync_commit() { asm volatile("cp.async.commit_group;"); }
__device__ __forceinline__ void cpasync_wait0()  { asm volatile("cp.async.wait_group 0;"); }
__device__ __forceinline__ void cpasync_wait1()  { asm volatile("cp.async.wait_group 1;"); }

__device__ __forceinline__ uint32_t smem_u32(const void* p) {
    uint32_t a;
    asm("{ .reg .u64 t; cvta.to.shared.u64 t, %1; cvt.u32.u64 %0, t; }" : "=r"(a) : "l"(p));
    return a;
}
__device__ __forceinline__ void ldsm_x4(uint32_t* r, uint32_t addr) {
    asm volatile("ldmatrix.sync.aligned.m8n8.x4.shared.b16 {%0,%1,%2,%3}, [%4];"
                 : "=r"(r[0]), "=r"(r[1]), "=r"(r[2]), "=r"(r[3]) : "r"(addr));
}
__device__ __forceinline__ void ldsm_x4_t(uint32_t* r, uint32_t addr) {
    asm volatile("ldmatrix.sync.aligned.m8n8.x4.trans.shared.b16 {%0,%1,%2,%3}, [%4];"
                 : "=r"(r[0]), "=r"(r[1]), "=r"(r[2]), "=r"(r[3]) : "r"(addr));
}
__device__ __forceinline__ void mma16816(float* c, const uint32_t* a, uint32_t b0, uint32_t b1) {
    asm volatile("mma.sync.aligned.m16n8k16.row.col.f32.bf16.bf16.f32 "
        "{%0,%1,%2,%3}, {%4,%5,%6,%7}, {%8,%9}, {%0,%1,%2,%3};"
        : "+f"(c[0]), "+f"(c[1]), "+f"(c[2]), "+f"(c[3])
        : "r"(a[0]), "r"(a[1]), "r"(a[2]), "r"(a[3]), "r"(b0), "r"(b1));
}

// ---------------- init ----------------
__global__ void __launch_bounds__(256) init_kernel(
    const float* __restrict__ s0, const float* __restrict__ s1,
    const float* __restrict__ s2)
{
    int idx = blockIdx.x * 256 + threadIdx.x;
    ((float4*)g_s1[0])[idx] = ((const float4*)s1)[idx];
    ((float4*)g_s2[0])[idx] = ((const float4*)s2)[idx];
    if (idx < BATCH * OUTD / 4)
        ((float4*)g_s0[0])[idx] = ((const float4*)s0)[idx];
}

// ---------------- build split weight images, [k][n] layout, swizzled ----------------
// element (k, n) at byte: k*512 + (((n>>3) ^ (k&7)) << 4) + (n&7)*2
__global__ void __launch_bounds__(H) img_kernel(const float* __restrict__ W2)
{
    int n = blockIdx.x, k = threadIdx.x;
    uint32_t off = (uint32_t)k * 512u + ((((uint32_t)n >> 3) ^ ((uint32_t)k & 7u)) << 4)
                 + ((uint32_t)n & 7u) * 2u;
    float w1 = W2[k * H + n];
    float w2 = W2[n * H + k];
    __nv_bfloat16 h1 = __float2bfloat16(w1);
    __nv_bfloat16 l1 = __float2bfloat16(w1 - __bfloat162float(h1));
    __nv_bfloat16 h2 = __float2bfloat16(w2);
    __nv_bfloat16 l2 = __float2bfloat16(w2 - __bfloat162float(h2));
    *(__nv_bfloat16*)((char*)g_B1hi + off) = h1;
    *(__nv_bfloat16*)((char*)g_B1lo + off) = l1;
    *(__nv_bfloat16*)((char*)g_B2hi + off) = h2;
    *(__nv_bfloat16*)((char*)g_B2lo + off) = l2;
}

// ---------------- prefix: X = rho(data) @ W4.T + b4 (fp32, once) ----------------
__global__ void __launch_bounds__(256) x_kernel(
    const float* __restrict__ data, const float* __restrict__ W4,
    const float* __restrict__ b4)
{
    __shared__ float As[16 * 66];
    __shared__ float Bs[16 * 66];
    const int tid = threadIdx.x;
    const int i0 = blockIdx.x * 64, j0 = blockIdx.y * 64;
    const int tx = tid & 15, ty = tid >> 4;
    const int kk = tid & 15, rr = tid >> 4;

    ull acc[4][2] = {};
    for (int k0 = 0; k0 < IND; k0 += 16) {
#pragma unroll
        for (int q = 0; q < 4; q++) {
            int r = rr + q * 16;
            As[kk * 66 + r] = rho_f(data[(size_t)(i0 + r) * IND + k0 + kk]);
            Bs[kk * 66 + r] = W4[(size_t)(j0 + r) * IND + k0 + kk];
        }
        __syncthreads();
#pragma unroll
        for (int k = 0; k < 16; k++) {
            ull a[4];
#pragma unroll
            for (int i = 0; i < 4; i++) {
                float av = As[k * 66 + ty * 4 + i];
                a[i] = pack2(av, av);
            }
            ull w0 = *(const ull*)(Bs + k * 66 + tx * 2);
            ull w1 = *(const ull*)(Bs + k * 66 + 32 + tx * 2);
#pragma unroll
            for (int i = 0; i < 4; i++) { fma2(acc[i][0], a[i], w0); fma2(acc[i][1], a[i], w1); }
        }
        __syncthreads();
    }
#pragma unroll
    for (int i = 0; i < 4; i++) {
        size_t row = (size_t)i0 + ty * 4 + i;
        float2 p0 = unpack2(acc[i][0]), p1 = unpack2(acc[i][1]);
        int j0a = j0 + tx * 2, j0b = j0 + 32 + tx * 2;
        *(float2*)(g_X + row * H + j0a) = make_float2(p0.x + b4[j0a], p0.y + b4[j0a + 1]);
        *(float2*)(g_X + row * H + j0b) = make_float2(p1.x + b4[j0b], p1.y + b4[j0b + 1]);
    }
}

// ---------------- SMEM layout (bytes) ----------------
#define SM_A_HI 0                      // [64][256] bf16 swizzled = 32KB
#define SM_A_LO 32768
#define SM_B    65536                  // 2 bufs x (hi 8KB + lo 8KB) = 32KB
#define SM_W0   98304                  // [10][256] f32 = 10KB
#define SM_RS0  (SM_W0 + OUTD * H * 4) // [64][10] f32
#define SM_B2V  (SM_RS0 + MROWS * OUTD * 4)
#define SM_B0V  (SM_B2V + H * 4)
#define SM_TOTAL (SM_B0V + 64)

// stage rho(state) [64][256] as bf16 hi/lo in swizzled row-major (k contiguous) layout
// element (m, k) at byte: m*512 + (((k>>3) ^ (m&7)) << 4) + (k&7)*2
__device__ __forceinline__ void stage_A(const float* __restrict__ sin, size_t row0,
                                        char* sm, int tid)
{
#pragma unroll
    for (int it = 0; it < 8; it++) {
        int idx = it * NTHR + tid;
        int m = idx >> 5, ch = idx & 31, k = ch << 3;
        float4 v0 = *(const float4*)(sin + (row0 + m) * H + k);
        float4 v1 = *(const float4*)(sin + (row0 + m) * H + k + 4);
        float f[8] = { rho_f(v0.x), rho_f(v0.y), rho_f(v0.z), rho_f(v0.w),
                       rho_f(v1.x), rho_f(v1.y), rho_f(v1.z), rho_f(v1.w) };
        uint32_t hi[4], lo[4];
#pragma unroll
        for (int q = 0; q < 4; q++) {
            __nv_bfloat16 ha = __float2bfloat16(f[2 * q]);
            __nv_bfloat16 hb = __float2bfloat16(f[2 * q + 1]);
            __nv_bfloat16 la = __float2bfloat16(f[2 * q] - __bfloat162float(ha));
            __nv_bfloat16 lb = __float2bfloat16(f[2 * q + 1] - __bfloat162float(hb));
            hi[q] = ((uint32_t)__bfloat16_as_ushort(hb) << 16) | __bfloat16_as_ushort(ha);
            lo[q] = ((uint32_t)__bfloat16_as_ushort(lb) << 16) | __bfloat16_as_ushort(la);
        }
        uint32_t off = (uint32_t)m * 512u + (((uint32_t)(ch ^ (m & 7))) << 4);
        *(uint4*)(sm + SM_A_HI + off) = make_uint4(hi[0], hi[1], hi[2], hi[3]);
        *(uint4*)(sm + SM_A_LO + off) = make_uint4(lo[0], lo[1], lo[2], lo[3]);
    }
}

__global__ void __launch_bounds__(NTHR, 2) step_kernel(
    int inbuf, int last, float* __restrict__ dout,
    const float* __restrict__ W0, const float* __restrict__ b0,
    const float* __restrict__ b2)
{
    extern __shared__ char sm[];
    const uint32_t smb = smem_u32(sm);
    const int tid = threadIdx.x;
    const int lane = tid & 31, wid = tid >> 5;
    const size_t row0 = (size_t)blockIdx.x * MROWS;

    const float* __restrict__ s0in = g_s0[inbuf];
    const float* __restrict__ s1in = g_s1[inbuf];
    const float* __restrict__ s2in = g_s2[inbuf];
    float* s0out = last ? dout : g_s0[inbuf ^ 1];
    float* s1out = last ? (dout + BATCH * OUTD) : g_s1[inbuf ^ 1];
    float* s2out = last ? (dout + BATCH * OUTD + (size_t)BATCH * H) : g_s2[inbuf ^ 1];

    // 8 warps: warp tile rows wm..wm+31 (wm in {0,32}), cols wn..wn+63
    const int wm = (wid & 1) * 32;
    const int wn = (wid >> 1) * 64;

    // small staging
    for (int i = tid; i < OUTD * H; i += NTHR) ((float*)(sm + SM_W0))[i] = W0[i];
    for (int i = tid; i < H; i += NTHR)        ((float*)(sm + SM_B2V))[i] = b2[i];
    if (tid < OUTD)                            ((float*)(sm + SM_B0V))[tid] = b0[tid];
    for (int i = tid; i < MROWS * OUTD; i += NTHR)
        ((float*)(sm + SM_RS0))[i] = rho_f(s0in[row0 * OUTD + i]);
    stage_A(s1in, row0, sm, tid);
    __syncthreads();

    float acc[2][8][4];

    for (int g = 0; g < 2; g++) {
        const char* imgHi = g ? (const char*)g_B2hi : (const char*)g_B1hi;
        const char* imgLo = g ? (const char*)g_B2lo : (const char*)g_B1lo;

#pragma unroll
        for (int i = 0; i < 2; i++)
#pragma unroll
            for (int j = 0; j < 8; j++)
#pragma unroll
                for (int q = 0; q < 4; q++) acc[i][j][q] = 0.f;

        // prefetch chunk 0 (16 k-rows: hi 8KB + lo 8KB) -> buf 0
        {
            char* d = sm + SM_B + tid * 32;
            cpasync16(d, imgHi + tid * 32);
            cpasync16(d + 16, imgHi + tid * 32 + 16);
            cpasync16(d + 8192, imgLo + tid * 32);
            cpasync16(d + 8192 + 16, imgLo + tid * 32 + 16);
            cpasync_commit();
        }

#pragma unroll 1
        for (int kc = 0; kc < 16; kc++) {
            const int buf = kc & 1;
            if (kc < 15) {
                char* d = sm + SM_B + (buf ^ 1) * 16384 + tid * 32;
                const char* sh = imgHi + (size_t)(kc + 1) * 8192 + tid * 32;
                const char* sl = imgLo + (size_t)(kc + 1) * 8192 + tid * 32;
                cpasync16(d, sh); cpasync16(d + 16, sh + 16);
                cpasync16(d + 8192, sl); cpasync16(d + 8192 + 16, sl + 16);
                cpasync_commit();
                cpasync_wait1();
            } else {
                cpasync_wait0();
            }
            __syncthreads();

            const uint32_t bbase = smb + SM_B + buf * 16384;
            const int kk = kc * 16;
            uint32_t ah[2][4], al[2][4];
#pragma unroll
            for (int i = 0; i < 2; i++) {
                int mr = wm + i * 16 + (lane & 15);
                uint32_t aoff = (uint32_t)mr * 512u
                              + ((uint32_t)(((kk >> 3) + (lane >> 4)) ^ (mr & 7)) << 4);
                ldsm_x4(ah[i], smb + SM_A_HI + aoff);
                ldsm_x4(al[i], smb + SM_A_LO + aoff);
            }
            const int kl = lane & 15;  // local k within chunk
#pragma unroll
            for (int jp = 0; jp < 4; jp++) {
                int nch = ((wn + jp * 16) >> 3) + (lane >> 4);
                uint32_t boff = (uint32_t)kl * 512u + ((uint32_t)(nch ^ (kl & 7)) << 4);
                uint32_t bh[4], bl[4];
                ldsm_x4_t(bh, bbase + boff);
                ldsm_x4_t(bl, bbase + 8192 + boff);
#pragma unroll
                for (int h = 0; h < 2; h++) {
                    int j = jp * 2 + h;
#pragma unroll
                    for (int i = 0; i < 2; i++) {
                        mma16816(acc[i][j], ah[i], bh[2 * h], bh[2 * h + 1]);
                        mma16816(acc[i][j], ah[i], bl[2 * h], bl[2 * h + 1]);
                        mma16816(acc[i][j], al[i], bh[2 * h], bh[2 * h + 1]);
                    }
                }
            }
            __syncthreads();
        }

        if (g == 0) {
            // ---- epilogue s2: s2' = rho(0.5*(s2 + rhop(s2)*(X + P2)))
#pragma unroll
            for (int i = 0; i < 2; i++) {
                int r = wm + i * 16 + (lane >> 2);
#pragma unroll
                for (int j = 0; j < 8; j++) {
                    int c = wn + j * 8 + 2 * (lane & 3);
#pragma unroll
                    for (int half = 0; half < 2; half++) {
                        size_t gr = row0 + r + half * 8;
                        float p0 = acc[i][j][half * 2], p1 = acc[i][j][half * 2 + 1];
                        float2 xo = *(const float2*)(g_X + gr * H + c);
                        float2 so = *(const float2*)(s2in + gr * H + c);
                        float2 ov;
                        ov.x = rho_f(0.5f * (so.x + ((so.x >= 0.f && so.x <= 1.f) ? (xo.x + p0) : 0.f)));
                        ov.y = rho_f(0.5f * (so.y + ((so.y >= 0.f && so.y <= 1.f) ? (xo.y + p1) : 0.f)));
                        *(float2*)(s2out + gr * H + c) = ov;
                    }
                }
            }
            // ---- s0 update: s0' = rho(0.5*(s0 + b0 + rho(s1) @ W0.T))
            const float* W0s = (const float*)(sm + SM_W0);
            const float* b0s = (const float*)(sm + SM_B0V);
            for (int task = tid; task < MROWS * OUTD; task += NTHR) {
                int r = task / OUTD, o = task - r * OUTD;
                const float* srow = s1in + (row0 + r) * H;
                const float* wrow = W0s + o * H;
                float a = b0s[o];
#pragma unroll 8
                for (int k = 0; k < H; k += 4) {
                    float4 sv = *(const float4*)(srow + k);
                    float4 wv = *(const float4*)(wrow + k);
                    a = fmaf(rho_f(sv.x), wv.x, fmaf(rho_f(sv.y), wv.y,
                        fmaf(rho_f(sv.z), wv.z, fmaf(rho_f(sv.w), wv.w, a))));
                }
                float s = s0in[(row0 + r) * OUTD + o];
                s0out[(row0 + r) * OUTD + o] = rho_f(0.5f * (s + a));
            }
            __syncthreads();
            stage_A(s2in, row0, sm, tid);
            __syncthreads();
        } else {
            // ---- epilogue s1: pre = P1 + b2 + rho(s0) @ W0
            const float* W0s = (const float*)(sm + SM_W0);
            const float* b2s = (const float*)(sm + SM_B2V);
            const float* rs0 = (const float*)(sm + SM_RS0);
#pragma unroll
            for (int i = 0; i < 2; i++) {
                int r = wm + i * 16 + (lane >> 2);
#pragma unroll
                for (int j = 0; j < 8; j++) {
                    int c = wn + j * 8 + 2 * (lane & 3);
                    float b2x = b2s[c], b2y = b2s[c + 1];
#pragma unroll
                    for (int half = 0; half < 2; half++) {
                        int rr = r + half * 8;
                        size_t gr = row0 + rr;
                        float p0 = acc[i][j][half * 2] + b2x;
                        float p1 = acc[i][j][half * 2 + 1] + b2y;
#pragma unroll
                        for (int o = 0; o < OUTD; o++) {
                            float a = rs0[rr * OUTD + o];
                            p0 = fmaf(a, W0s[o * H + c], p0);
                            p1 = fmaf(a, W0s[o * H + c + 1], p1);
                        }
                        float2 so = *(const float2*)(s1in + gr * H + c);
                        float2 ov;
                        ov.x = rho_f(0.5f * (so.x + ((so.x >= 0.f && so.x <= 1.f) ? p0 : 0.f)));
                        ov.y = rho_f(0.5f * (so.y + ((so.y >= 0.f && so.y <= 1.f) ? p1 : 0.f)));
                        *(float2*)(s1out + gr * H + c) = ov;
                    }
                }
            }
        }
    }
}

// ---------------- launch ----------------
extern "C" void kernel_launch(void* const* d_in, const int* in_sizes, int n_in,
                              void* d_out, int out_size)
{
    (void)in_sizes; (void)n_in; (void)out_size;
    const float* data = (const float*)d_in[0];
    const float* s0   = (const float*)d_in[1];
    const float* s1   = (const float*)d_in[2];
    const float* s2   = (const float*)d_in[3];
    const float* W0   = (const float*)d_in[4];
    const float* b0   = (const float*)d_in[5];
    const float* W2   = (const float*)d_in[6];
    const float* b2   = (const float*)d_in[7];
    const float* W4   = (const float*)d_in[8];
    const float* b4   = (const float*)d_in[9];
    float* out = (float*)d_out;

    cudaFuncSetAttribute(step_kernel, cudaFuncAttributeMaxDynamicSharedMemorySize, SM_TOTAL);

    init_kernel<<<(BATCH * H / 4) / 256, 256>>>(s0, s1, s2);
    img_kernel<<<H, H>>>(W2);
    x_kernel<<<dim3(BATCH / 64, H / 64), 256>>>(data, W4, b4);
    for (int t = 0; t < TSTEPS; t++) {
        step_kernel<<<BATCH / MROWS, NTHR, SM_TOTAL>>>(
            t & 1, t == TSTEPS - 1, out, W0, b0, b2);
    }
}

// round 9
// speedup vs baseline: 1.5164x; 1.5164x over previous
#include <cuda_runtime.h>
#include <cuda_bf16.h>
#include <cstdint>

#define BATCH 16384
#define H 256
#define OUTD 10
#define IND 784
#define TSTEPS 50
#define MROWS 128
#define NTHR 512

typedef unsigned long long ull;

// -------- device scratch --------
__device__ float g_X[BATCH * H];
__device__ float g_s0[2][BATCH * OUTD];
__device__ float g_s1[2][BATCH * H];
__device__ float g_s2[2][BATCH * H];
// bf16 split weight images in [k][n] layout (n contiguous), XOR-swizzled 16B chunks.
// B1[k][n] = W2[k][n]  (P2 = rho(s1) @ W2);  B2[k][n] = W2[n][k]  (P1 = rho(s2) @ W2^T)
__device__ __nv_bfloat16 g_B1hi[H * H], g_B1lo[H * H], g_B2hi[H * H], g_B2lo[H * H];

__device__ __forceinline__ float rho_f(float x) { return fminf(fmaxf(x, 0.0f), 1.0f); }

__device__ __forceinline__ ull pack2(float a, float b) {
    ull r; asm("mov.b64 %0, {%1, %2};" : "=l"(r) : "f"(a), "f"(b)); return r;
}
__device__ __forceinline__ void fma2(ull &d, ull a, ull b) {
    asm("fma.rn.f32x2 %0, %1, %2, %0;" : "+l"(d) : "l"(a), "l"(b));
}
__device__ __forceinline__ float2 unpack2(ull v) {
    float2 f; asm("mov.b64 {%0, %1}, %2;" : "=f"(f.x), "=f"(f.y) : "l"(v)); return f;
}
__device__ __forceinline__ void cpasync16(char* dst, const char* src) {
    unsigned d = (unsigned)__cvta_generic_to_shared(dst);
    asm volatile("cp.async.cg.shared.global [%0], [%1], 16;" :: "r"(d), "l"(src));
}
__device__ __forceinline__ void cpasync_commit() { asm volatile("cp.async.commit_group;"); }
__device__ __forceinline__ void cpasync_wait0()  { asm volatile("cp.async.wait_group 0;"); }

__device__ __forceinline__ uint32_t smem_u32(const void* p) {
    uint32_t a;
    asm("{ .reg .u64 t; cvta.to.shared.u64 t, %1; cvt.u32.u64 %0, t; }" : "=r"(a) : "l"(p));
    return a;
}
__device__ __forceinline__ void ldsm_x4(uint32_t* r, uint32_t addr) {
    asm volatile("ldmatrix.sync.aligned.m8n8.x4.shared.b16 {%0,%1,%2,%3}, [%4];"
                 : "=r"(r[0]), "=r"(r[1]), "=r"(r[2]), "=r"(r[3]) : "r"(addr));
}
__device__ __forceinline__ void ldsm_x4_t(uint32_t* r, uint32_t addr) {
    asm volatile("ldmatrix.sync.aligned.m8n8.x4.trans.shared.b16 {%0,%1,%2,%3}, [%4];"
                 : "=r"(r[0]), "=r"(r[1]), "=r"(r[2]), "=r"(r[3]) : "r"(addr));
}
__device__ __forceinline__ void mma16816(float* c, const uint32_t* a, uint32_t b0, uint32_t b1) {
    asm volatile("mma.sync.aligned.m16n8k16.row.col.f32.bf16.bf16.f32 "
        "{%0,%1,%2,%3}, {%4,%5,%6,%7}, {%8,%9}, {%0,%1,%2,%3};"
        : "+f"(c[0]), "+f"(c[1]), "+f"(c[2]), "+f"(c[3])
        : "r"(a[0]), "r"(a[1]), "r"(a[2]), "r"(a[3]), "r"(b0), "r"(b1));
}

// ---------------- init ----------------
__global__ void __launch_bounds__(256) init_kernel(
    const float* __restrict__ s0, const float* __restrict__ s1,
    const float* __restrict__ s2)
{
    int idx = blockIdx.x * 256 + threadIdx.x;
    ((float4*)g_s1[0])[idx] = ((const float4*)s1)[idx];
    ((float4*)g_s2[0])[idx] = ((const float4*)s2)[idx];
    if (idx < BATCH * OUTD / 4)
        ((float4*)g_s0[0])[idx] = ((const float4*)s0)[idx];
}

// ---------------- build split weight images, [k][n] layout, swizzled ----------------
// element (k, n) at byte: k*512 + (((n>>3) ^ (k&7)) << 4) + (n&7)*2
__global__ void __launch_bounds__(H) img_kernel(const float* __restrict__ W2)
{
    int n = blockIdx.x, k = threadIdx.x;
    uint32_t off = (uint32_t)k * 512u + ((((uint32_t)n >> 3) ^ ((uint32_t)k & 7u)) << 4)
                 + ((uint32_t)n & 7u) * 2u;
    float w1 = W2[k * H + n];
    float w2 = W2[n * H + k];
    __nv_bfloat16 h1 = __float2bfloat16(w1);
    __nv_bfloat16 l1 = __float2bfloat16(w1 - __bfloat162float(h1));
    __nv_bfloat16 h2 = __float2bfloat16(w2);
    __nv_bfloat16 l2 = __float2bfloat16(w2 - __bfloat162float(h2));
    *(__nv_bfloat16*)((char*)g_B1hi + off) = h1;
    *(__nv_bfloat16*)((char*)g_B1lo + off) = l1;
    *(__nv_bfloat16*)((char*)g_B2hi + off) = h2;
    *(__nv_bfloat16*)((char*)g_B2lo + off) = l2;
}

// ---------------- prefix: X = rho(data) @ W4.T + b4 (fp32, once) ----------------
__global__ void __launch_bounds__(256) x_kernel(
    const float* __restrict__ data, const float* __restrict__ W4,
    const float* __restrict__ b4)
{
    __shared__ float As[16 * 66];
    __shared__ float Bs[16 * 66];
    const int tid = threadIdx.x;
    const int i0 = blockIdx.x * 64, j0 = blockIdx.y * 64;
    const int tx = tid & 15, ty = tid >> 4;
    const int kk = tid & 15, rr = tid >> 4;

    ull acc[4][2] = {};
    for (int k0 = 0; k0 < IND; k0 += 16) {
#pragma unroll
        for (int q = 0; q < 4; q++) {
            int r = rr + q * 16;
            As[kk * 66 + r] = rho_f(data[(size_t)(i0 + r) * IND + k0 + kk]);
            Bs[kk * 66 + r] = W4[(size_t)(j0 + r) * IND + k0 + kk];
        }
        __syncthreads();
#pragma unroll
        for (int k = 0; k < 16; k++) {
            ull a[4];
#pragma unroll
            for (int i = 0; i < 4; i++) {
                float av = As[k * 66 + ty * 4 + i];
                a[i] = pack2(av, av);
            }
            ull w0 = *(const ull*)(Bs + k * 66 + tx * 2);
            ull w1 = *(const ull*)(Bs + k * 66 + 32 + tx * 2);
#pragma unroll
            for (int i = 0; i < 4; i++) { fma2(acc[i][0], a[i], w0); fma2(acc[i][1], a[i], w1); }
        }
        __syncthreads();
    }
#pragma unroll
    for (int i = 0; i < 4; i++) {
        size_t row = (size_t)i0 + ty * 4 + i;
        float2 p0 = unpack2(acc[i][0]), p1 = unpack2(acc[i][1]);
        int j0a = j0 + tx * 2, j0b = j0 + 32 + tx * 2;
        *(float2*)(g_X + row * H + j0a) = make_float2(p0.x + b4[j0a], p0.y + b4[j0a + 1]);
        *(float2*)(g_X + row * H + j0b) = make_float2(p1.x + b4[j0b], p1.y + b4[j0b + 1]);
    }
}

// ---------------- SMEM layout (bytes) ----------------
#define SM_A_HI 0                      // [128][256] bf16 swizzled = 64KB
#define SM_A_LO 65536
#define SM_B    131072                 // 2 bufs x (hi 16KB + lo 16KB) = 64KB
#define SM_W0   196608                 // [10][256] f32
#define SM_RS0  (SM_W0 + OUTD * H * 4) // [128][10] f32
#define SM_B2V  (SM_RS0 + MROWS * OUTD * 4)
#define SM_B0V  (SM_B2V + H * 4)
#define SM_TOTAL (SM_B0V + 64)

// stage rho(state) [128][256] as bf16 hi/lo in swizzled row-major (k contiguous) layout
// element (m, k) at byte: m*512 + (((k>>3) ^ (m&7)) << 4) + (k&7)*2
__device__ __forceinline__ void stage_A(const float* __restrict__ sin, size_t row0,
                                        char* sm, int tid)
{
#pragma unroll
    for (int it = 0; it < 8; it++) {
        int idx = it * NTHR + tid;
        int m = idx >> 5, ch = idx & 31, k = ch << 3;
        float4 v0 = *(const float4*)(sin + (row0 + m) * H + k);
        float4 v1 = *(const float4*)(sin + (row0 + m) * H + k + 4);
        float f[8] = { rho_f(v0.x), rho_f(v0.y), rho_f(v0.z), rho_f(v0.w),
                       rho_f(v1.x), rho_f(v1.y), rho_f(v1.z), rho_f(v1.w) };
        uint32_t hi[4], lo[4];
#pragma unroll
        for (int q = 0; q < 4; q++) {
            __nv_bfloat16 ha = __float2bfloat16(f[2 * q]);
            __nv_bfloat16 hb = __float2bfloat16(f[2 * q + 1]);
            __nv_bfloat16 la = __float2bfloat16(f[2 * q] - __bfloat162float(ha));
            __nv_bfloat16 lb = __float2bfloat16(f[2 * q + 1] - __bfloat162float(hb));
            hi[q] = ((uint32_t)__bfloat16_as_ushort(hb) << 16) | __bfloat16_as_ushort(ha);
            lo[q] = ((uint32_t)__bfloat16_as_ushort(lb) << 16) | __bfloat16_as_ushort(la);
        }
        uint32_t off = (uint32_t)m * 512u + (((uint32_t)(ch ^ (m & 7))) << 4);
        *(uint4*)(sm + SM_A_HI + off) = make_uint4(hi[0], hi[1], hi[2], hi[3]);
        *(uint4*)(sm + SM_A_LO + off) = make_uint4(lo[0], lo[1], lo[2], lo[3]);
    }
}

// prefetch one 32-k chunk (hi 16KB + lo 16KB) into buffer buf
__device__ __forceinline__ void prefetch_chunk(char* sm, int buf, int tid,
                                               const char* imgHi, const char* imgLo,
                                               int chunk)
{
    char* d = sm + SM_B + buf * 32768 + tid * 32;
    const char* sh = imgHi + (size_t)chunk * 16384 + tid * 32;
    const char* sl = imgLo + (size_t)chunk * 16384 + tid * 32;
    cpasync16(d, sh); cpasync16(d + 16, sh + 16);
    cpasync16(d + 16384, sl); cpasync16(d + 16384 + 16, sl + 16);
    cpasync_commit();
}

__global__ void __launch_bounds__(NTHR, 1) step_kernel(
    int inbuf, int last, float* __restrict__ dout,
    const float* __restrict__ W0, const float* __restrict__ b0,
    const float* __restrict__ b2)
{
    extern __shared__ char sm[];
    const uint32_t smb = smem_u32(sm);
    const int tid = threadIdx.x;
    const int lane = tid & 31, wid = tid >> 5;
    const size_t row0 = (size_t)blockIdx.x * MROWS;

    const float* __restrict__ s0in = g_s0[inbuf];
    const float* __restrict__ s1in = g_s1[inbuf];
    const float* __restrict__ s2in = g_s2[inbuf];
    float* s0out = last ? dout : g_s0[inbuf ^ 1];
    float* s1out = last ? (dout + BATCH * OUTD) : g_s1[inbuf ^ 1];
    float* s2out = last ? (dout + BATCH * OUTD + (size_t)BATCH * H) : g_s2[inbuf ^ 1];

    // warp tile: rows wm..wm+31, cols wn..wn+63
    const int wm = (wid & 3) * 32;
    const int wn = (wid >> 2) * 64;

    // small staging
    for (int i = tid; i < OUTD * H; i += NTHR) ((float*)(sm + SM_W0))[i] = W0[i];
    for (int i = tid; i < H; i += NTHR)        ((float*)(sm + SM_B2V))[i] = b2[i];
    if (tid < OUTD)                            ((float*)(sm + SM_B0V))[tid] = b0[tid];
    for (int i = tid; i < MROWS * OUTD; i += NTHR)
        ((float*)(sm + SM_RS0))[i] = rho_f(s0in[row0 * OUTD + i]);
    stage_A(s1in, row0, sm, tid);

    // prefetch GEMM0 chunk0 -> buf0 (before the sync; A-stage sync covers visibility)
    prefetch_chunk(sm, 0, tid, (const char*)g_B1hi, (const char*)g_B1lo, 0);
    __syncthreads();

    float acc[2][8][4];

    for (int g = 0; g < 2; g++) {
        const char* imgHi = g ? (const char*)g_B2hi : (const char*)g_B1hi;
        const char* imgLo = g ? (const char*)g_B2lo : (const char*)g_B1lo;

#pragma unroll
        for (int i = 0; i < 2; i++)
#pragma unroll
            for (int j = 0; j < 8; j++)
#pragma unroll
                for (int q = 0; q < 4; q++) acc[i][j][q] = 0.f;

#pragma unroll 1
        for (int kc = 0; kc < 8; kc++) {
            const int buf = kc & 1;
            // wait for THIS chunk's cp.async, then one sync (covers buffer reuse too)
            cpasync_wait0();
            __syncthreads();
            // prefetch next chunk (same GEMM), or the next GEMM's chunk0 at the seam
            if (kc < 7)
                prefetch_chunk(sm, buf ^ 1, tid, imgHi, imgLo, kc + 1);
            else if (g == 0)
                prefetch_chunk(sm, buf ^ 1, tid, (const char*)g_B2hi, (const char*)g_B2lo, 0);

            const uint32_t bbase = smb + SM_B + buf * 32768;
#pragma unroll
            for (int ks = 0; ks < 2; ks++) {
                const int kk = kc * 32 + ks * 16;
                uint32_t ah[2][4], al[2][4];
#pragma unroll
                for (int i = 0; i < 2; i++) {
                    int mr = wm + i * 16 + (lane & 15);
                    uint32_t aoff = (uint32_t)mr * 512u
                                  + ((uint32_t)(((kk >> 3) + (lane >> 4)) ^ (mr & 7)) << 4);
                    ldsm_x4(ah[i], smb + SM_A_HI + aoff);
                    ldsm_x4(al[i], smb + SM_A_LO + aoff);
                }
                const int kl = ks * 16 + (lane & 15);
#pragma unroll
                for (int jp = 0; jp < 4; jp++) {
                    int nch = ((wn + jp * 16) >> 3) + (lane >> 4);
                    uint32_t boff = (uint32_t)kl * 512u
                                  + ((uint32_t)(nch ^ (kl & 7)) << 4);
                    uint32_t bh[4], bl[4];
                    ldsm_x4_t(bh, bbase + boff);
                    ldsm_x4_t(bl, bbase + 16384 + boff);
                    // term-major order: same-acc MMAs spaced 4 apart for ILP
#pragma unroll
                    for (int h = 0; h < 2; h++)
#pragma unroll
                        for (int i = 0; i < 2; i++)
                            mma16816(acc[i][jp * 2 + h], ah[i], bh[2 * h], bh[2 * h + 1]);
#pragma unroll
                    for (int h = 0; h < 2; h++)
#pragma unroll
                        for (int i = 0; i < 2; i++)
                            mma16816(acc[i][jp * 2 + h], ah[i], bl[2 * h], bl[2 * h + 1]);
#pragma unroll
                    for (int h = 0; h < 2; h++)
#pragma unroll
                        for (int i = 0; i < 2; i++)
                            mma16816(acc[i][jp * 2 + h], al[i], bh[2 * h], bh[2 * h + 1]);
                }
            }
            // no trailing sync: next iteration's wait+sync protects buffer reuse
        }

        if (g == 0) {
            // ---- epilogue s2: s2' = rho(0.5*(s2 + rhop(s2)*(X + P2)))
#pragma unroll
            for (int i = 0; i < 2; i++) {
                int r = wm + i * 16 + (lane >> 2);
#pragma unroll
                for (int j = 0; j < 8; j++) {
                    int c = wn + j * 8 + 2 * (lane & 3);
#pragma unroll
                    for (int half = 0; half < 2; half++) {
                        size_t gr = row0 + r + half * 8;
                        float p0 = acc[i][j][half * 2], p1 = acc[i][j][half * 2 + 1];
                        float2 xo = *(const float2*)(g_X + gr * H + c);
                        float2 so = *(const float2*)(s2in + gr * H + c);
                        float2 ov;
                        ov.x = rho_f(0.5f * (so.x + ((so.x >= 0.f && so.x <= 1.f) ? (xo.x + p0) : 0.f)));
                        ov.y = rho_f(0.5f * (so.y + ((so.y >= 0.f && so.y <= 1.f) ? (xo.y + p1) : 0.f)));
                        *(float2*)(s2out + gr * H + c) = ov;
                    }
                }
            }
            // ---- s0 update: s0' = rho(0.5*(s0 + b0 + rho(s1) @ W0.T))
            const float* W0s = (const float*)(sm + SM_W0);
            const float* b0s = (const float*)(sm + SM_B0V);
            for (int task = tid; task < MROWS * OUTD; task += NTHR) {
                int r = task / OUTD, o = task - r * OUTD;
                const float* srow = s1in + (row0 + r) * H;
                const float* wrow = W0s + o * H;
                float a = b0s[o];
#pragma unroll 8
                for (int k = 0; k < H; k += 4) {
                    float4 sv = *(const float4*)(srow + k);
                    float4 wv = *(const float4*)(wrow + k);
                    a = fmaf(rho_f(sv.x), wv.x, fmaf(rho_f(sv.y), wv.y,
                        fmaf(rho_f(sv.z), wv.z, fmaf(rho_f(sv.w), wv.w, a))));
                }
                float s = s0in[(row0 + r) * OUTD + o];
                s0out[(row0 + r) * OUTD + o] = rho_f(0.5f * (s + a));
            }
            __syncthreads();           // all warps done with A (g0 mma) before restage
            stage_A(s2in, row0, sm, tid);
            __syncthreads();
        } else {
            // ---- epilogue s1: pre = P1 + b2 + rho(s0) @ W0
            const float* W0s = (const float*)(sm + SM_W0);
            const float* b2s = (const float*)(sm + SM_B2V);
            const float* rs0 = (const float*)(sm + SM_RS0);
#pragma unroll
            for (int i = 0; i < 2; i++) {
                int r = wm + i * 16 + (lane >> 2);
#pragma unroll
                for (int j = 0; j < 8; j++) {
                    int c = wn + j * 8 + 2 * (lane & 3);
                    float b2x = b2s[c], b2y = b2s[c + 1];
#pragma unroll
                    for (int half = 0; half < 2; half++) {
                        int rr = r + half * 8;
                        size_t gr = row0 + rr;
                        float p0 = acc[i][j][half * 2] + b2x;
                        float p1 = acc[i][j][half * 2 + 1] + b2y;
#pragma unroll
                        for (int o = 0; o < OUTD; o++) {
                            float a = rs0[rr * OUTD + o];
                            p0 = fmaf(a, W0s[o * H + c], p0);
                            p1 = fmaf(a, W0s[o * H + c + 1], p1);
                        }
                        float2 so = *(const float2*)(s1in + gr * H + c);
                        float2 ov;
                        ov.x = rho_f(0.5f * (so.x + ((so.x >= 0.f && so.x <= 1.f) ? p0 : 0.f)));
                        ov.y = rho_f(0.5f * (so.y + ((so.y >= 0.f && so.y <= 1.f) ? p1 : 0.f)));
                        *(float2*)(s1out + gr * H + c) = ov;
                    }
                }
            }
        }
    }
}

// ---------------- launch ----------------
extern "C" void kernel_launch(void* const* d_in, const int* in_sizes, int n_in,
                              void* d_out, int out_size)
{
    (void)in_sizes; (void)n_in; (void)out_size;
    const float* data = (const float*)d_in[0];
    const float* s0   = (const float*)d_in[1];
    const float* s1   = (const float*)d_in[2];
    const float* s2   = (const float*)d_in[3];
    const float* W0   = (const float*)d_in[4];
    const float* b0   = (const float*)d_in[5];
    const float* W2   = (const float*)d_in[6];
    const float* b2   = (const float*)d_in[7];
    const float* W4   = (const float*)d_in[8];
    const float* b4   = (const float*)d_in[9];
    float* out = (float*)d_out;

    cudaFuncSetAttribute(step_kernel, cudaFuncAttributeMaxDynamicSharedMemorySize, SM_TOTAL);

    init_kernel<<<(BATCH * H / 4) / 256, 256>>>(s0, s1, s2);
    img_kernel<<<H, H>>>(W2);
    x_kernel<<<dim3(BATCH / 64, H / 64), 256>>>(data, W4, b4);
    for (int t = 0; t < TSTEPS; t++) {
        step_kernel<<<BATCH / MROWS, NTHR, SM_TOTAL>>>(
            t & 1, t == TSTEPS - 1, out, W0, b0, b2);
    }
}

// round 10
// speedup vs baseline: 1.8772x; 1.2379x over previous
#include <cuda_runtime.h>
#include <cuda_fp16.h>
#include <cstdint>

#define BATCH 16384
#define H 256
#define OUTD 10
#define IND 784
#define TSTEPS 50
#define MROWS 128
#define NTHR 512

typedef unsigned long long ull;

// -------- device scratch --------
__device__ float g_X[BATCH * H];
__device__ float g_s0[2][BATCH * OUTD];
__device__ float g_s1[2][BATCH * H];
__device__ float g_s2[2][BATCH * H];
// fp16 weight images in [k][n] layout (n contiguous), XOR-swizzled 16B chunks.
// B1[k][n] = W2[k][n]  (P2 = rho(s1) @ W2);  B2[k][n] = W2[n][k]  (P1 = rho(s2) @ W2^T)
__device__ __half g_B1[H * H], g_B2[H * H];

__device__ __forceinline__ float rho_f(float x) { return fminf(fmaxf(x, 0.0f), 1.0f); }

__device__ __forceinline__ ull pack2(float a, float b) {
    ull r; asm("mov.b64 %0, {%1, %2};" : "=l"(r) : "f"(a), "f"(b)); return r;
}
__device__ __forceinline__ void fma2(ull &d, ull a, ull b) {
    asm("fma.rn.f32x2 %0, %1, %2, %0;" : "+l"(d) : "l"(a), "l"(b));
}
__device__ __forceinline__ float2 unpack2(ull v) {
    float2 f; asm("mov.b64 {%0, %1}, %2;" : "=f"(f.x), "=f"(f.y) : "l"(v)); return f;
}
__device__ __forceinline__ void cpasync16(char* dst, const char* src) {
    unsigned d = (unsigned)__cvta_generic_to_shared(dst);
    asm volatile("cp.async.cg.shared.global [%0], [%1], 16;" :: "r"(d), "l"(src));
}
__device__ __forceinline__ void cpasync_commit() { asm volatile("cp.async.commit_group;"); }
__device__ __forceinline__ void cpasync_wait0()  { asm volatile("cp.async.wait_group 0;"); }

__device__ __forceinline__ uint32_t smem_u32(const void* p) {
    uint32_t a;
    asm("{ .reg .u64 t; cvta.to.shared.u64 t, %1; cvt.u32.u64 %0, t; }" : "=r"(a) : "l"(p));
    return a;
}
__device__ __forceinline__ void ldsm_x4(uint32_t* r, uint32_t addr) {
    asm volatile("ldmatrix.sync.aligned.m8n8.x4.shared.b16 {%0,%1,%2,%3}, [%4];"
                 : "=r"(r[0]), "=r"(r[1]), "=r"(r[2]), "=r"(r[3]) : "r"(addr));
}
__device__ __forceinline__ void ldsm_x4_t(uint32_t* r, uint32_t addr) {
    asm volatile("ldmatrix.sync.aligned.m8n8.x4.trans.shared.b16 {%0,%1,%2,%3}, [%4];"
                 : "=r"(r[0]), "=r"(r[1]), "=r"(r[2]), "=r"(r[3]) : "r"(addr));
}
__device__ __forceinline__ void mma16816(float* c, const uint32_t* a, uint32_t b0, uint32_t b1) {
    asm volatile("mma.sync.aligned.m16n8k16.row.col.f32.f16.f16.f32 "
        "{%0,%1,%2,%3}, {%4,%5,%6,%7}, {%8,%9}, {%0,%1,%2,%3};"
        : "+f"(c[0]), "+f"(c[1]), "+f"(c[2]), "+f"(c[3])
        : "r"(a[0]), "r"(a[1]), "r"(a[2]), "r"(a[3]), "r"(b0), "r"(b1));
}

// ---------------- init ----------------
__global__ void __launch_bounds__(256) init_kernel(
    const float* __restrict__ s0, const float* __restrict__ s1,
    const float* __restrict__ s2)
{
    int idx = blockIdx.x * 256 + threadIdx.x;
    ((float4*)g_s1[0])[idx] = ((const float4*)s1)[idx];
    ((float4*)g_s2[0])[idx] = ((const float4*)s2)[idx];
    if (idx < BATCH * OUTD / 4)
        ((float4*)g_s0[0])[idx] = ((const float4*)s0)[idx];
}

// ---------------- build fp16 weight images, [k][n] layout, swizzled ----------------
// element (k, n) at byte: k*512 + (((n>>3) ^ (k&7)) << 4) + (n&7)*2
__global__ void __launch_bounds__(H) img_kernel(const float* __restrict__ W2)
{
    int n = blockIdx.x, k = threadIdx.x;
    uint32_t off = (uint32_t)k * 512u + ((((uint32_t)n >> 3) ^ ((uint32_t)k & 7u)) << 4)
                 + ((uint32_t)n & 7u) * 2u;
    *(__half*)((char*)g_B1 + off) = __float2half(W2[k * H + n]);
    *(__half*)((char*)g_B2 + off) = __float2half(W2[n * H + k]);
}

// ---------------- prefix: X = rho(data) @ W4.T + b4 (fp32, once) ----------------
__global__ void __launch_bounds__(256) x_kernel(
    const float* __restrict__ data, const float* __restrict__ W4,
    const float* __restrict__ b4)
{
    __shared__ float As[16 * 66];
    __shared__ float Bs[16 * 66];
    const int tid = threadIdx.x;
    const int i0 = blockIdx.x * 64, j0 = blockIdx.y * 64;
    const int tx = tid & 15, ty = tid >> 4;
    const int kk = tid & 15, rr = tid >> 4;

    ull acc[4][2] = {};
    for (int k0 = 0; k0 < IND; k0 += 16) {
#pragma unroll
        for (int q = 0; q < 4; q++) {
            int r = rr + q * 16;
            As[kk * 66 + r] = rho_f(data[(size_t)(i0 + r) * IND + k0 + kk]);
            Bs[kk * 66 + r] = W4[(size_t)(j0 + r) * IND + k0 + kk];
        }
        __syncthreads();
#pragma unroll
        for (int k = 0; k < 16; k++) {
            ull a[4];
#pragma unroll
            for (int i = 0; i < 4; i++) {
                float av = As[k * 66 + ty * 4 + i];
                a[i] = pack2(av, av);
            }
            ull w0 = *(const ull*)(Bs + k * 66 + tx * 2);
            ull w1 = *(const ull*)(Bs + k * 66 + 32 + tx * 2);
#pragma unroll
            for (int i = 0; i < 4; i++) { fma2(acc[i][0], a[i], w0); fma2(acc[i][1], a[i], w1); }
        }
        __syncthreads();
    }
#pragma unroll
    for (int i = 0; i < 4; i++) {
        size_t row = (size_t)i0 + ty * 4 + i;
        float2 p0 = unpack2(acc[i][0]), p1 = unpack2(acc[i][1]);
        int j0a = j0 + tx * 2, j0b = j0 + 32 + tx * 2;
        *(float2*)(g_X + row * H + j0a) = make_float2(p0.x + b4[j0a], p0.y + b4[j0a + 1]);
        *(float2*)(g_X + row * H + j0b) = make_float2(p1.x + b4[j0b], p1.y + b4[j0b + 1]);
    }
}

// ---------------- SMEM layout (bytes) ----------------
#define SM_A    0                      // [128][256] fp16 swizzled = 64KB
#define SM_B    65536                  // 2 bufs x 16KB = 32KB
#define SM_W0   98304                  // [10][256] f32
#define SM_RS0  (SM_W0 + OUTD * H * 4) // [128][10] f32
#define SM_B2V  (SM_RS0 + MROWS * OUTD * 4)
#define SM_B0V  (SM_B2V + H * 4)
#define SM_TOTAL (SM_B0V + 64)

// stage rho(state) [128][256] as fp16 in swizzled row-major (k contiguous) layout
// element (m, k) at byte: m*512 + (((k>>3) ^ (m&7)) << 4) + (k&7)*2
__device__ __forceinline__ void stage_A(const float* __restrict__ sin, size_t row0,
                                        char* sm, int tid)
{
#pragma unroll
    for (int it = 0; it < 8; it++) {
        int idx = it * NTHR + tid;
        int m = idx >> 5, ch = idx & 31, k = ch << 3;
        float4 v0 = *(const float4*)(sin + (row0 + m) * H + k);
        float4 v1 = *(const float4*)(sin + (row0 + m) * H + k + 4);
        float f[8] = { rho_f(v0.x), rho_f(v0.y), rho_f(v0.z), rho_f(v0.w),
                       rho_f(v1.x), rho_f(v1.y), rho_f(v1.z), rho_f(v1.w) };
        uint32_t h[4];
#pragma unroll
        for (int q = 0; q < 4; q++) {
            __half ha = __float2half(f[2 * q]);
            __half hb = __float2half(f[2 * q + 1]);
            h[q] = ((uint32_t)__half_as_ushort(hb) << 16) | __half_as_ushort(ha);
        }
        uint32_t off = (uint32_t)m * 512u + (((uint32_t)(ch ^ (m & 7))) << 4);
        *(uint4*)(sm + SM_A + off) = make_uint4(h[0], h[1], h[2], h[3]);
    }
}

// prefetch one 32-k chunk (16KB) into buffer buf
__device__ __forceinline__ void prefetch_chunk(char* sm, int buf, int tid,
                                               const char* img, int chunk)
{
    char* d = sm + SM_B + buf * 16384 + tid * 32;
    const char* s = img + (size_t)chunk * 16384 + tid * 32;
    cpasync16(d, s); cpasync16(d + 16, s + 16);
    cpasync_commit();
}

__global__ void __launch_bounds__(NTHR, 1) step_kernel(
    int inbuf, int last, float* __restrict__ dout,
    const float* __restrict__ W0, const float* __restrict__ b0,
    const float* __restrict__ b2)
{
    extern __shared__ char sm[];
    const uint32_t smb = smem_u32(sm);
    const int tid = threadIdx.x;
    const int lane = tid & 31, wid = tid >> 5;
    const size_t row0 = (size_t)blockIdx.x * MROWS;

    const float* __restrict__ s0in = g_s0[inbuf];
    const float* __restrict__ s1in = g_s1[inbuf];
    const float* __restrict__ s2in = g_s2[inbuf];
    float* s0out = last ? dout : g_s0[inbuf ^ 1];
    float* s1out = last ? (dout + BATCH * OUTD) : g_s1[inbuf ^ 1];
    float* s2out = last ? (dout + BATCH * OUTD + (size_t)BATCH * H) : g_s2[inbuf ^ 1];

    // warp tile: rows wm..wm+31, cols wn..wn+63
    const int wm = (wid & 3) * 32;
    const int wn = (wid >> 2) * 64;

    // small staging
    for (int i = tid; i < OUTD * H; i += NTHR) ((float*)(sm + SM_W0))[i] = W0[i];
    for (int i = tid; i < H; i += NTHR)        ((float*)(sm + SM_B2V))[i] = b2[i];
    if (tid < OUTD)                            ((float*)(sm + SM_B0V))[tid] = b0[tid];
    for (int i = tid; i < MROWS * OUTD; i += NTHR)
        ((float*)(sm + SM_RS0))[i] = rho_f(s0in[row0 * OUTD + i]);
    stage_A(s1in, row0, sm, tid);

    // prefetch GEMM0 chunk0 -> buf0 (A-stage sync covers visibility)
    prefetch_chunk(sm, 0, tid, (const char*)g_B1, 0);
    __syncthreads();

    float acc[2][8][4];

    for (int g = 0; g < 2; g++) {
        const char* img = g ? (const char*)g_B2 : (const char*)g_B1;

#pragma unroll
        for (int i = 0; i < 2; i++)
#pragma unroll
            for (int j = 0; j < 8; j++)
#pragma unroll
                for (int q = 0; q < 4; q++) acc[i][j][q] = 0.f;

#pragma unroll 1
        for (int kc = 0; kc < 8; kc++) {
            const int buf = kc & 1;
            cpasync_wait0();
            __syncthreads();
            if (kc < 7)
                prefetch_chunk(sm, buf ^ 1, tid, img, kc + 1);
            else if (g == 0)
                prefetch_chunk(sm, buf ^ 1, tid, (const char*)g_B2, 0);

            const uint32_t bbase = smb + SM_B + buf * 16384;
#pragma unroll
            for (int ks = 0; ks < 2; ks++) {
                const int kk = kc * 32 + ks * 16;
                uint32_t ah[2][4];
#pragma unroll
                for (int i = 0; i < 2; i++) {
                    int mr = wm + i * 16 + (lane & 15);
                    uint32_t aoff = (uint32_t)mr * 512u
                                  + ((uint32_t)(((kk >> 3) + (lane >> 4)) ^ (mr & 7)) << 4);
                    ldsm_x4(ah[i], smb + SM_A + aoff);
                }
                const int kl = ks * 16 + (lane & 15);
#pragma unroll
                for (int jp = 0; jp < 4; jp++) {
                    int nch = ((wn + jp * 16) >> 3) + (lane >> 4);
                    uint32_t boff = (uint32_t)kl * 512u
                                  + ((uint32_t)(nch ^ (kl & 7)) << 4);
                    uint32_t bh[4];
                    ldsm_x4_t(bh, bbase + boff);
#pragma unroll
                    for (int h = 0; h < 2; h++)
#pragma unroll
                        for (int i = 0; i < 2; i++)
                            mma16816(acc[i][jp * 2 + h], ah[i], bh[2 * h], bh[2 * h + 1]);
                }
            }
        }

        if (g == 0) {
            // ---- epilogue s2: s2' = rho(0.5*(s2 + rhop(s2)*(X + P2)))
#pragma unroll
            for (int i = 0; i < 2; i++) {
                int r = wm + i * 16 + (lane >> 2);
#pragma unroll
                for (int j = 0; j < 8; j++) {
                    int c = wn + j * 8 + 2 * (lane & 3);
#pragma unroll
                    for (int half = 0; half < 2; half++) {
                        size_t gr = row0 + r + half * 8;
                        float p0 = acc[i][j][half * 2], p1 = acc[i][j][half * 2 + 1];
                        float2 xo = *(const float2*)(g_X + gr * H + c);
                        float2 so = *(const float2*)(s2in + gr * H + c);
                        float2 ov;
                        ov.x = rho_f(0.5f * (so.x + ((so.x >= 0.f && so.x <= 1.f) ? (xo.x + p0) : 0.f)));
                        ov.y = rho_f(0.5f * (so.y + ((so.y >= 0.f && so.y <= 1.f) ? (xo.y + p1) : 0.f)));
                        *(float2*)(s2out + gr * H + c) = ov;
                    }
                }
            }
            // ---- s0 update: s0' = rho(0.5*(s0 + b0 + rho(s1) @ W0.T))
            const float* W0s = (const float*)(sm + SM_W0);
            const float* b0s = (const float*)(sm + SM_B0V);
            for (int task = tid; task < MROWS * OUTD; task += NTHR) {
                int r = task / OUTD, o = task - r * OUTD;
                const float* srow = s1in + (row0 + r) * H;
                const float* wrow = W0s + o * H;
                float a = b0s[o];
#pragma unroll 8
                for (int k = 0; k < H; k += 4) {
                    float4 sv = *(const float4*)(srow + k);
                    float4 wv = *(const float4*)(wrow + k);
                    a = fmaf(rho_f(sv.x), wv.x, fmaf(rho_f(sv.y), wv.y,
                        fmaf(rho_f(sv.z), wv.z, fmaf(rho_f(sv.w), wv.w, a))));
                }
                float s = s0in[(row0 + r) * OUTD + o];
                s0out[(row0 + r) * OUTD + o] = rho_f(0.5f * (s + a));
            }
            __syncthreads();           // all warps done with A (g0 mma) before restage
            stage_A(s2in, row0, sm, tid);
            __syncthreads();
        } else {
            // ---- epilogue s1: pre = P1 + b2 + rho(s0) @ W0
            const float* W0s = (const float*)(sm + SM_W0);
            const float* b2s = (const float*)(sm + SM_B2V);
            const float* rs0 = (const float*)(sm + SM_RS0);
#pragma unroll
            for (int i = 0; i < 2; i++) {
                int r = wm + i * 16 + (lane >> 2);
#pragma unroll
                for (int j = 0; j < 8; j++) {
                    int c = wn + j * 8 + 2 * (lane & 3);
                    float b2x = b2s[c], b2y = b2s[c + 1];
#pragma unroll
                    for (int half = 0; half < 2; half++) {
                        int rr = r + half * 8;
                        size_t gr = row0 + rr;
                        float p0 = acc[i][j][half * 2] + b2x;
                        float p1 = acc[i][j][half * 2 + 1] + b2y;
#pragma unroll
                        for (int o = 0; o < OUTD; o++) {
                            float a = rs0[rr * OUTD + o];
                            p0 = fmaf(a, W0s[o * H + c], p0);
                            p1 = fmaf(a, W0s[o * H + c + 1], p1);
                        }
                        float2 so = *(const float2*)(s1in + gr * H + c);
                        float2 ov;
                        ov.x = rho_f(0.5f * (so.x + ((so.x >= 0.f && so.x <= 1.f) ? p0 : 0.f)));
                        ov.y = rho_f(0.5f * (so.y + ((so.y >= 0.f && so.y <= 1.f) ? p1 : 0.f)));
                        *(float2*)(s1out + gr * H + c) = ov;
                    }
                }
            }
        }
    }
}

// ---------------- launch ----------------
extern "C" void kernel_launch(void* const* d_in, const int* in_sizes, int n_in,
                              void* d_out, int out_size)
{
    (void)in_sizes; (void)n_in; (void)out_size;
    const float* data = (const float*)d_in[0];
    const float* s0   = (const float*)d_in[1];
    const float* s1   = (const float*)d_in[2];
    const float* s2   = (const float*)d_in[3];
    const float* W0   = (const float*)d_in[4];
    const float* b0   = (const float*)d_in[5];
    const float* W2   = (const float*)d_in[6];
    const float* b2   = (const float*)d_in[7];
    const float* W4   = (const float*)d_in[8];
    const float* b4   = (const float*)d_in[9];
    float* out = (float*)d_out;

    cudaFuncSetAttribute(step_kernel, cudaFuncAttributeMaxDynamicSharedMemorySize, SM_TOTAL);

    init_kernel<<<(BATCH * H / 4) / 256, 256>>>(s0, s1, s2);
    img_kernel<<<H, H>>>(W2);
    x_kernel<<<dim3(BATCH / 64, H / 64), 256>>>(data, W4, b4);
    for (int t = 0; t < TSTEPS; t++) {
        step_kernel<<<BATCH / MROWS, NTHR, SM_TOTAL>>>(
            t & 1, t == TSTEPS - 1, out, W0, b0, b2);
    }
}

// round 11
// speedup vs baseline: 3.4849x; 1.8565x over previous
#include <cuda_runtime.h>
#include <cuda_fp16.h>
#include <cstdint>

#define BATCH 16384
#define H 256
#define H2 288
#define OUTD 10
#define IND 784
#define TSTEPS 50
#define MROWS 128
#define NTHR 512

typedef unsigned long long ull;

// -------- device scratch --------
__device__ float g_X[BATCH * H];
__device__ float g_s0[2][BATCH * OUTD];
__device__ float g_s1[2][BATCH * H];
__device__ float g_s2[2][BATCH * H];
// fp16 weight images in [k][n] layout (n contiguous), XOR-swizzled 16B chunks.
// B1[k][n] = W2[k][n]  (P2 = rho(s1) @ W2)
// B2e: rows 0..255 = W2[n][k] (P1 = rho(s2) @ W2^T); rows 256+o = W0[o][n];
//      row 266 = b2[n]; rows 267..287 = 0   (extra chunk folds b2 + rho(s0)@W0)
__device__ __half g_B1[H * H], g_B2e[H2 * H];

__device__ __forceinline__ float rho_f(float x) { return fminf(fmaxf(x, 0.0f), 1.0f); }

__device__ __forceinline__ ull pack2(float a, float b) {
    ull r; asm("mov.b64 %0, {%1, %2};" : "=l"(r) : "f"(a), "f"(b)); return r;
}
__device__ __forceinline__ void fma2(ull &d, ull a, ull b) {
    asm("fma.rn.f32x2 %0, %1, %2, %0;" : "+l"(d) : "l"(a), "l"(b));
}
__device__ __forceinline__ float2 unpack2(ull v) {
    float2 f; asm("mov.b64 {%0, %1}, %2;" : "=f"(f.x), "=f"(f.y) : "l"(v)); return f;
}
__device__ __forceinline__ void cpasync16(char* dst, const char* src) {
    unsigned d = (unsigned)__cvta_generic_to_shared(dst);
    asm volatile("cp.async.cg.shared.global [%0], [%1], 16;" :: "r"(d), "l"(src));
}
__device__ __forceinline__ void cpasync_commit() { asm volatile("cp.async.commit_group;"); }
__device__ __forceinline__ void cpasync_wait0()  { asm volatile("cp.async.wait_group 0;"); }

__device__ __forceinline__ uint32_t smem_u32(const void* p) {
    uint32_t a;
    asm("{ .reg .u64 t; cvta.to.shared.u64 t, %1; cvt.u32.u64 %0, t; }" : "=r"(a) : "l"(p));
    return a;
}
__device__ __forceinline__ void ldsm_x4(uint32_t* r, uint32_t addr) {
    asm volatile("ldmatrix.sync.aligned.m8n8.x4.shared.b16 {%0,%1,%2,%3}, [%4];"
                 : "=r"(r[0]), "=r"(r[1]), "=r"(r[2]), "=r"(r[3]) : "r"(addr));
}
__device__ __forceinline__ void ldsm_x4_t(uint32_t* r, uint32_t addr) {
    asm volatile("ldmatrix.sync.aligned.m8n8.x4.trans.shared.b16 {%0,%1,%2,%3}, [%4];"
                 : "=r"(r[0]), "=r"(r[1]), "=r"(r[2]), "=r"(r[3]) : "r"(addr));
}
__device__ __forceinline__ void mma16816(float* c, const uint32_t* a, uint32_t b0, uint32_t b1) {
    asm volatile("mma.sync.aligned.m16n8k16.row.col.f32.f16.f16.f32 "
        "{%0,%1,%2,%3}, {%4,%5,%6,%7}, {%8,%9}, {%0,%1,%2,%3};"
        : "+f"(c[0]), "+f"(c[1]), "+f"(c[2]), "+f"(c[3])
        : "r"(a[0]), "r"(a[1]), "r"(a[2]), "r"(a[3]), "r"(b0), "r"(b1));
}
__device__ __forceinline__ uint32_t pack_h2(float a, float b) {
    __half ha = __float2half(a), hb = __float2half(b);
    return ((uint32_t)__half_as_ushort(hb) << 16) | __half_as_ushort(ha);
}

// ---------------- init ----------------
__global__ void __launch_bounds__(256) init_kernel(
    const float* __restrict__ s0, const float* __restrict__ s1,
    const float* __restrict__ s2)
{
    int idx = blockIdx.x * 256 + threadIdx.x;
    ((float4*)g_s1[0])[idx] = ((const float4*)s1)[idx];
    ((float4*)g_s2[0])[idx] = ((const float4*)s2)[idx];
    if (idx < BATCH * OUTD / 4)
        ((float4*)g_s0[0])[idx] = ((const float4*)s0)[idx];
}

// ---------------- build fp16 weight images, [k][n] layout, swizzled ----------------
// element (k, n) at byte: k*512 + (((n>>3) ^ (k&7)) << 4) + (n&7)*2
__global__ void __launch_bounds__(H2) img_kernel(
    const float* __restrict__ W2, const float* __restrict__ W0,
    const float* __restrict__ b2)
{
    int n = blockIdx.x, k = threadIdx.x;
    uint32_t off = (uint32_t)k * 512u + ((((uint32_t)n >> 3) ^ ((uint32_t)k & 7u)) << 4)
                 + ((uint32_t)n & 7u) * 2u;
    if (k < H)
        *(__half*)((char*)g_B1 + off) = __float2half(W2[k * H + n]);
    float w;
    if (k < H)              w = W2[n * H + k];
    else if (k < H + OUTD)  w = W0[(k - H) * H + n];
    else if (k == H + OUTD) w = b2[n];
    else                    w = 0.f;
    *(__half*)((char*)g_B2e + off) = __float2half(w);
}

// ---------------- prefix: X = rho(data) @ W4.T + b4 (fp32, once) ----------------
__global__ void __launch_bounds__(256) x_kernel(
    const float* __restrict__ data, const float* __restrict__ W4,
    const float* __restrict__ b4)
{
    __shared__ float As[16 * 66];
    __shared__ float Bs[16 * 66];
    const int tid = threadIdx.x;
    const int i0 = blockIdx.x * 64, j0 = blockIdx.y * 64;
    const int tx = tid & 15, ty = tid >> 4;
    const int kk = tid & 15, rr = tid >> 4;

    ull acc[4][2] = {};
    for (int k0 = 0; k0 < IND; k0 += 16) {
#pragma unroll
        for (int q = 0; q < 4; q++) {
            int r = rr + q * 16;
            As[kk * 66 + r] = rho_f(data[(size_t)(i0 + r) * IND + k0 + kk]);
            Bs[kk * 66 + r] = W4[(size_t)(j0 + r) * IND + k0 + kk];
        }
        __syncthreads();
#pragma unroll
        for (int k = 0; k < 16; k++) {
            ull a[4];
#pragma unroll
            for (int i = 0; i < 4; i++) {
                float av = As[k * 66 + ty * 4 + i];
                a[i] = pack2(av, av);
            }
            ull w0 = *(const ull*)(Bs + k * 66 + tx * 2);
            ull w1 = *(const ull*)(Bs + k * 66 + 32 + tx * 2);
#pragma unroll
            for (int i = 0; i < 4; i++) { fma2(acc[i][0], a[i], w0); fma2(acc[i][1], a[i], w1); }
        }
        __syncthreads();
    }
#pragma unroll
    for (int i = 0; i < 4; i++) {
        size_t row = (size_t)i0 + ty * 4 + i;
        float2 p0 = unpack2(acc[i][0]), p1 = unpack2(acc[i][1]);
        int j0a = j0 + tx * 2, j0b = j0 + 32 + tx * 2;
        *(float2*)(g_X + row * H + j0a) = make_float2(p0.x + b4[j0a], p0.y + b4[j0a + 1]);
        *(float2*)(g_X + row * H + j0b) = make_float2(p1.x + b4[j0b], p1.y + b4[j0b + 1]);
    }
}

// ---------------- SMEM layout (bytes) ----------------
#define SM_A1   0                      // [128][256] fp16 swizzled = 64KB  (rho(s1))
#define SM_A2   65536                  // 64KB (rho(s2))
#define SM_B    131072                 // 2 bufs x 16KB = 32KB
#define SM_W0   163840                 // [10][256] f32 = 10240
#define SM_RS0  174080                 // [128][10] f32 = 5120
#define SM_B0V  179200
#define SM_TOTAL (SM_B0V + 64)

// stage rho(state) [128][256] as fp16 in swizzled row-major layout
// element (m, k) at byte: m*512 + (((k>>3) ^ (m&7)) << 4) + (k&7)*2
__device__ __forceinline__ void stage_A(const float* __restrict__ sin, size_t row0,
                                        char* smA, int tid)
{
#pragma unroll
    for (int it = 0; it < 8; it++) {
        int idx = it * NTHR + tid;
        int m = idx >> 5, ch = idx & 31, k = ch << 3;
        float4 v0 = *(const float4*)(sin + (row0 + m) * H + k);
        float4 v1 = *(const float4*)(sin + (row0 + m) * H + k + 4);
        float f[8] = { rho_f(v0.x), rho_f(v0.y), rho_f(v0.z), rho_f(v0.w),
                       rho_f(v1.x), rho_f(v1.y), rho_f(v1.z), rho_f(v1.w) };
        uint32_t h[4];
#pragma unroll
        for (int q = 0; q < 4; q++)
            h[q] = pack_h2(f[2 * q], f[2 * q + 1]);
        uint32_t off = (uint32_t)m * 512u + (((uint32_t)(ch ^ (m & 7))) << 4);
        *(uint4*)(smA + off) = make_uint4(h[0], h[1], h[2], h[3]);
    }
}

// prefetch one 32-k chunk (16KB) into buffer buf
__device__ __forceinline__ void prefetch_chunk(char* sm, int buf, int tid,
                                               const char* img, int chunk)
{
    char* d = sm + SM_B + buf * 16384 + tid * 32;
    const char* s = img + (size_t)chunk * 16384 + tid * 32;
    cpasync16(d, s); cpasync16(d + 16, s + 16);
    cpasync_commit();
}

__global__ void __launch_bounds__(NTHR, 1) step_kernel(
    int inbuf, int last, float* __restrict__ dout,
    const float* __restrict__ W0, const float* __restrict__ b0)
{
    extern __shared__ char sm[];
    const uint32_t smb = smem_u32(sm);
    const int tid = threadIdx.x;
    const int lane = tid & 31, wid = tid >> 5;
    const size_t row0 = (size_t)blockIdx.x * MROWS;

    const float* __restrict__ s0in = g_s0[inbuf];
    const float* __restrict__ s1in = g_s1[inbuf];
    const float* __restrict__ s2in = g_s2[inbuf];
    float* s0out = last ? dout : g_s0[inbuf ^ 1];
    float* s1out = last ? (dout + BATCH * OUTD) : g_s1[inbuf ^ 1];
    float* s2out = last ? (dout + BATCH * OUTD + (size_t)BATCH * H) : g_s2[inbuf ^ 1];

    // warp tile: rows wm..wm+31, cols wn..wn+63
    const int wm = (wid & 3) * 32;
    const int wn = (wid >> 2) * 64;

    // small staging
    for (int i = tid; i < OUTD * H; i += NTHR) ((float*)(sm + SM_W0))[i] = W0[i];
    if (tid < OUTD)                            ((float*)(sm + SM_B0V))[tid] = b0[tid];
    for (int i = tid; i < MROWS * OUTD; i += NTHR)
        ((float*)(sm + SM_RS0))[i] = rho_f(s0in[row0 * OUTD + i]);
    // both A tiles upfront
    stage_A(s1in, row0, sm + SM_A1, tid);
    stage_A(s2in, row0, sm + SM_A2, tid);
    prefetch_chunk(sm, 0, tid, (const char*)g_B1, 0);
    __syncthreads();

    float acc[2][8][4];

    for (int g = 0; g < 2; g++) {
        const char* img = g ? (const char*)g_B2e : (const char*)g_B1;
        const uint32_t abase = smb + (g ? SM_A2 : SM_A1);
        const int nchunks = g ? 9 : 8;

#pragma unroll
        for (int i = 0; i < 2; i++)
#pragma unroll
            for (int j = 0; j < 8; j++)
#pragma unroll
                for (int q = 0; q < 4; q++) acc[i][j][q] = 0.f;

#pragma unroll 1
        for (int kc = 0; kc < nchunks; kc++) {
            const int buf = kc & 1;
            cpasync_wait0();
            __syncthreads();
            if (kc < nchunks - 1)
                prefetch_chunk(sm, buf ^ 1, tid, img, kc + 1);
            else if (g == 0)
                prefetch_chunk(sm, buf ^ 1, tid, (const char*)g_B2e, 0);

            const uint32_t bbase = smb + SM_B + buf * 16384;

            if (g == 1 && kc == 8) {
                // extra chunk: A = [rs0 | 1 | 0] composed in regs; only ks=0 (k-rows 256..271)
                const float* rs0 = (const float*)(sm + SM_RS0);
                const int t = lane & 3, gq = lane >> 2;
                uint32_t ae[2][4];
#pragma unroll
                for (int i = 0; i < 2; i++) {
                    int r0 = wm + i * 16 + gq, r1 = r0 + 8;
                    float v00 = rs0[r0 * OUTD + 2 * t], v01 = rs0[r0 * OUTD + 2 * t + 1];
                    float v10 = rs0[r1 * OUTD + 2 * t], v11 = rs0[r1 * OUTD + 2 * t + 1];
                    float v02, v03, v12, v13;
                    if (t == 0) {
                        v02 = rs0[r0 * OUTD + 8]; v03 = rs0[r0 * OUTD + 9];
                        v12 = rs0[r1 * OUTD + 8]; v13 = rs0[r1 * OUTD + 9];
                    } else if (t == 1) {
                        v02 = 1.f; v03 = 0.f; v12 = 1.f; v13 = 0.f;
                    } else {
                        v02 = v03 = v12 = v13 = 0.f;
                    }
                    ae[i][0] = pack_h2(v00, v01); ae[i][1] = pack_h2(v10, v11);
                    ae[i][2] = pack_h2(v02, v03); ae[i][3] = pack_h2(v12, v13);
                }
                const int kl = lane & 15;
#pragma unroll
                for (int jp = 0; jp < 4; jp++) {
                    int nch = ((wn + jp * 16) >> 3) + (lane >> 4);
                    uint32_t boff = (uint32_t)kl * 512u + ((uint32_t)(nch ^ (kl & 7)) << 4);
                    uint32_t bh[4];
                    ldsm_x4_t(bh, bbase + boff);
#pragma unroll
                    for (int h = 0; h < 2; h++)
#pragma unroll
                        for (int i = 0; i < 2; i++)
                            mma16816(acc[i][jp * 2 + h], ae[i], bh[2 * h], bh[2 * h + 1]);
                }
            } else {
#pragma unroll
                for (int ks = 0; ks < 2; ks++) {
                    const int kk = kc * 32 + ks * 16;
                    uint32_t ah[2][4];
#pragma unroll
                    for (int i = 0; i < 2; i++) {
                        int mr = wm + i * 16 + (lane & 15);
                        uint32_t aoff = (uint32_t)mr * 512u
                                      + ((uint32_t)(((kk >> 3) + (lane >> 4)) ^ (mr & 7)) << 4);
                        ldsm_x4(ah[i], abase + aoff);
                    }
                    const int kl = ks * 16 + (lane & 15);
#pragma unroll
                    for (int jp = 0; jp < 4; jp++) {
                        int nch = ((wn + jp * 16) >> 3) + (lane >> 4);
                        uint32_t boff = (uint32_t)kl * 512u
                                      + ((uint32_t)(nch ^ (kl & 7)) << 4);
                        uint32_t bh[4];
                        ldsm_x4_t(bh, bbase + boff);
#pragma unroll
                        for (int h = 0; h < 2; h++)
#pragma unroll
                            for (int i = 0; i < 2; i++)
                                mma16816(acc[i][jp * 2 + h], ah[i], bh[2 * h], bh[2 * h + 1]);
                    }
                }
            }
        }

        if (g == 0) {
            // ---- epilogue s2: s2' = rho(0.5*(s2 + rhop(s2)*(X + P2)))
#pragma unroll
            for (int i = 0; i < 2; i++) {
                int r = wm + i * 16 + (lane >> 2);
#pragma unroll
                for (int j = 0; j < 8; j++) {
                    int c = wn + j * 8 + 2 * (lane & 3);
#pragma unroll
                    for (int half = 0; half < 2; half++) {
                        size_t gr = row0 + r + half * 8;
                        float p0 = acc[i][j][half * 2], p1 = acc[i][j][half * 2 + 1];
                        float2 xo = *(const float2*)(g_X + gr * H + c);
                        float2 so = *(const float2*)(s2in + gr * H + c);
                        float2 ov;
                        ov.x = rho_f(0.5f * (so.x + ((so.x >= 0.f && so.x <= 1.f) ? (xo.x + p0) : 0.f)));
                        ov.y = rho_f(0.5f * (so.y + ((so.y >= 0.f && so.y <= 1.f) ? (xo.y + p1) : 0.f)));
                        *(float2*)(s2out + gr * H + c) = ov;
                    }
                }
            }
            // ---- s0 update: warp-per-row, W0 in regs, shuffle reduce
            {
                const float* W0s = (const float*)(sm + SM_W0);
                const float* b0s = (const float*)(sm + SM_B0V);
                float4 wreg[OUTD][2];
#pragma unroll
                for (int o = 0; o < OUTD; o++) {
                    wreg[o][0] = *(const float4*)(W0s + o * H + lane * 8);
                    wreg[o][1] = *(const float4*)(W0s + o * H + lane * 8 + 4);
                }
#pragma unroll 1
                for (int rr = 0; rr < 8; rr++) {
                    int r = wid * 8 + rr;
                    const float* srow = s1in + (row0 + r) * H + lane * 8;
                    float4 v0 = *(const float4*)srow;
                    float4 v1 = *(const float4*)(srow + 4);
                    v0.x = rho_f(v0.x); v0.y = rho_f(v0.y); v0.z = rho_f(v0.z); v0.w = rho_f(v0.w);
                    v1.x = rho_f(v1.x); v1.y = rho_f(v1.y); v1.z = rho_f(v1.z); v1.w = rho_f(v1.w);
                    float accs[OUTD];
#pragma unroll
                    for (int o = 0; o < OUTD; o++) {
                        float4 w0 = wreg[o][0], w1 = wreg[o][1];
                        accs[o] = v0.x * w0.x + v0.y * w0.y + v0.z * w0.z + v0.w * w0.w
                                + v1.x * w1.x + v1.y * w1.y + v1.z * w1.z + v1.w * w1.w;
                    }
#pragma unroll
                    for (int d = 16; d; d >>= 1)
#pragma unroll
                        for (int o = 0; o < OUTD; o++)
                            accs[o] += __shfl_xor_sync(0xffffffffu, accs[o], d);
                    if (lane == 0) {
#pragma unroll
                        for (int o = 0; o < OUTD; o++) {
                            float s = s0in[(row0 + r) * OUTD + o];
                            s0out[(row0 + r) * OUTD + o] = rho_f(0.5f * (s + accs[o] + b0s[o]));
                        }
                    }
                }
            }
        } else {
            // ---- epilogue s1: pre = P1 (b2 + rho(s0)@W0 folded into GEMM)
#pragma unroll
            for (int i = 0; i < 2; i++) {
                int r = wm + i * 16 + (lane >> 2);
#pragma unroll
                for (int j = 0; j < 8; j++) {
                    int c = wn + j * 8 + 2 * (lane & 3);
#pragma unroll
                    for (int half = 0; half < 2; half++) {
                        size_t gr = row0 + r + half * 8;
                        float p0 = acc[i][j][half * 2], p1 = acc[i][j][half * 2 + 1];
                        float2 so = *(const float2*)(s1in + gr * H + c);
                        float2 ov;
                        ov.x = rho_f(0.5f * (so.x + ((so.x >= 0.f && so.x <= 1.f) ? p0 : 0.f)));
                        ov.y = rho_f(0.5f * (so.y + ((so.y >= 0.f && so.y <= 1.f) ? p1 : 0.f)));
                        *(float2*)(s1out + gr * H + c) = ov;
                    }
                }
            }
        }
    }
}

// ---------------- launch ----------------
extern "C" void kernel_launch(void* const* d_in, const int* in_sizes, int n_in,
                              void* d_out, int out_size)
{
    (void)in_sizes; (void)n_in; (void)out_size;
    const float* data = (const float*)d_in[0];
    const float* s0   = (const float*)d_in[1];
    const float* s1   = (const float*)d_in[2];
    const float* s2   = (const float*)d_in[3];
    const float* W0   = (const float*)d_in[4];
    const float* b0   = (const float*)d_in[5];
    const float* W2   = (const float*)d_in[6];
    const float* b2   = (const float*)d_in[7];
    const float* W4   = (const float*)d_in[8];
    const float* b4   = (const float*)d_in[9];
    float* out = (float*)d_out;

    cudaFuncSetAttribute(step_kernel, cudaFuncAttributeMaxDynamicSharedMemorySize, SM_TOTAL);

    init_kernel<<<(BATCH * H / 4) / 256, 256>>>(s0, s1, s2);
    img_kernel<<<H, H2>>>(W2, W0, b2);
    x_kernel<<<dim3(BATCH / 64, H / 64), 256>>>(data, W4, b4);
    for (int t = 0; t < TSTEPS; t++) {
        step_kernel<<<BATCH / MROWS, NTHR, SM_TOTAL>>>(
            t & 1, t == TSTEPS - 1, out, W0, b0);
    }
}